// round 2
// baseline (speedup 1.0000x reference)
#include <cuda_runtime.h>
#include <math.h>

// Problem constants
#define B_  2
#define L_  2048
#define H_  1024
#define NH_ 16
#define HD_ 64
#define BH_ (B_*NH_)          // 32
#define M_  (B_*L_)           // 4096
#define MAXPOS_ 2048

// Scratch (device globals — allocation-free contract)
__device__ float g_q[(size_t)BH_*L_*HD_];       // [bh][l][hd]
__device__ float g_k[(size_t)BH_*L_*HD_];
__device__ float g_v[(size_t)BH_*L_*HD_];
__device__ float g_scores[(size_t)BH_*L_*L_];   // [bh][l][r]  (536 MB)

// ---------------------------------------------------------------------------
// Kernel A: fused QKV projection.  out = hidden @ W^T + b, written to head
// layout [bh][l][hd].  GEMM M=4096 N=1024 K=1024, per blockIdx.z weight.
// BM=128 BN=64 BK=16, 128 threads, 8x8 per thread.
// ---------------------------------------------------------------------------
__global__ __launch_bounds__(128) void qkv_kernel(
    const float* __restrict__ hidden,
    const float* __restrict__ Wq, const float* __restrict__ bq,
    const float* __restrict__ Wk, const float* __restrict__ bk,
    const float* __restrict__ Wv, const float* __restrict__ bv)
{
    __shared__ float Ast[16][132];   // [k][m-row]
    __shared__ float Bst[16][68];    // [k][n-col]

    const int which = blockIdx.z;
    const float* W   = (which == 0) ? Wq : (which == 1) ? Wk : Wv;
    const float* bia = (which == 0) ? bq : (which == 1) ? bk : bv;
    float* out       = (which == 0) ? g_q : (which == 1) ? g_k : g_v;

    const int m0 = blockIdx.y * 128;
    const int n0 = blockIdx.x * 64;
    const int t  = threadIdx.x;
    const int ty = t >> 3;          // 0..15  -> 8 rows each
    const int tx = t & 7;           // 0..7   -> 8 cols each
    const int lc = t & 15;          // load col (k)
    const int lr = t >> 4;          // load row base 0..7

    float acc[8][8];
#pragma unroll
    for (int i = 0; i < 8; i++)
#pragma unroll
        for (int j = 0; j < 8; j++) acc[i][j] = 0.f;

    for (int k0 = 0; k0 < H_; k0 += 16) {
#pragma unroll
        for (int it = 0; it < 16; it++)
            Ast[lc][lr + it*8] = hidden[(size_t)(m0 + lr + it*8)*H_ + k0 + lc];
#pragma unroll
        for (int it = 0; it < 8; it++)
            Bst[lc][lr + it*8] = W[(size_t)(n0 + lr + it*8)*H_ + k0 + lc];
        __syncthreads();
#pragma unroll
        for (int k = 0; k < 16; k++) {
            float a[8], b[8];
            *(float4*)&a[0] = *(const float4*)&Ast[k][ty*8];
            *(float4*)&a[4] = *(const float4*)&Ast[k][ty*8 + 4];
            *(float4*)&b[0] = *(const float4*)&Bst[k][tx*8];
            *(float4*)&b[4] = *(const float4*)&Bst[k][tx*8 + 4];
#pragma unroll
            for (int i = 0; i < 8; i++)
#pragma unroll
                for (int j = 0; j < 8; j++) acc[i][j] = fmaf(a[i], b[j], acc[i][j]);
        }
        __syncthreads();
    }

    // epilogue: head layout. h is constant per block (n0 multiple of 64).
    const int h = n0 >> 6;
#pragma unroll
    for (int i = 0; i < 8; i++) {
        const int m  = m0 + ty*8 + i;
        const int b_ = m >> 11;
        const int l  = m & (L_-1);
        float* orow = out + (((size_t)(b_*NH_ + h))*L_ + l)*HD_;
#pragma unroll
        for (int j = 0; j < 8; j++) {
            const int nn = tx*8 + j;                 // hd
            orow[nn] = acc[i][j] + bia[n0 + nn];
        }
    }
}

// ---------------------------------------------------------------------------
// Kernel B: fused scores = (q.k + q.e + k.e) * 1/sqrt(HD) + mask.
// 64x64 tile per block, 256 threads, 4x4 per thread.
// e-slab: 127 diagonal rows of dist_emb staged in SMEM, layout [t][dd] so the
// inner loop reads contiguous float4s along the diagonal index.
// Dynamic SMEM: qst[64][68] + kst[64][68] + est[64][128]  = 66 KB.
// ---------------------------------------------------------------------------
#define SMEM_B_BYTES ((2*64*68 + 64*128)*4)

__global__ __launch_bounds__(256) void scores_kernel(
    const float* __restrict__ mask,
    const float* __restrict__ dist_emb)
{
    extern __shared__ float sm[];
    float* qst = sm;                 // [t][i]  stride 68
    float* kst = sm + 64*68;         // [t][j]  stride 68
    float* est = sm + 2*64*68;       // [t][dd] stride 128

    const int bh = blockIdx.z;
    const int l0 = blockIdx.y * 64;
    const int r0 = blockIdx.x * 64;
    const int t  = threadIdx.x;
    const int tx = t & 15;
    const int ty = t >> 4;

    const float* q = g_q + (size_t)bh * L_ * HD_;
    const float* k = g_k + (size_t)bh * L_ * HD_;

    // load q/k tiles transposed: [hd][row]
    {
        const int col  = t & 63;      // hd
        const int row4 = t >> 6;      // 0..3
#pragma unroll
        for (int it = 0; it < 16; it++) {
            const int r_ = row4 + it*4;
            qst[col*68 + r_] = q[(size_t)(l0 + r_)*HD_ + col];
            kst[col*68 + r_] = k[(size_t)(r0 + r_)*HD_ + col];
        }
    }
    // e slab: global diag rows gbase..gbase+126, always within [0,4094]
    {
        const int gbase = l0 - r0 + (MAXPOS_ - 1) - 63;   // l0-r0+1984
        for (int idx = t; idx < 64*128; idx += 256) {
            const int dd = idx & 127;
            const int tc = idx >> 7;
            est[tc*128 + dd] = (dd < 127) ? dist_emb[(size_t)(gbase + dd)*HD_ + tc] : 0.f;
        }
    }
    __syncthreads();

    float acc[4][4];
#pragma unroll
    for (int i = 0; i < 4; i++)
#pragma unroll
        for (int j = 0; j < 4; j++) acc[i][j] = 0.f;

    const int qb = ty*4, kb = tx*4;
    const int dbase = (ty - tx)*4 + 60;      // 0..120, mult of 4

    for (int tt = 0; tt < 64; tt++) {
        float qv[4], kv[4], ev[8];
        *(float4*)&qv[0] = *(const float4*)&qst[tt*68 + qb];
        *(float4*)&kv[0] = *(const float4*)&kst[tt*68 + kb];
        *(float4*)&ev[0] = *(const float4*)&est[tt*128 + dbase];
        *(float4*)&ev[4] = *(const float4*)&est[tt*128 + dbase + 4];
#pragma unroll
        for (int i = 0; i < 4; i++)
#pragma unroll
            for (int j = 0; j < 4; j++) {
                const int m = i - j + 3;     // 0..6 -> ev[m] = e[l-r]
                acc[i][j] = fmaf(qv[i], kv[j], acc[i][j]);
                acc[i][j] = fmaf(qv[i] + kv[j], ev[m], acc[i][j]);
            }
    }

    const float* maskrow = mask + (size_t)(bh >> 4) * L_;  // [B,1,1,L]
    const float scale = 0.125f;                            // 1/sqrt(64)
#pragma unroll
    for (int i = 0; i < 4; i++) {
        const int l = l0 + qb + i;
        float* srow = g_scores + ((size_t)bh * L_ + l) * L_ + r0 + kb;
        float4 v;
        v.x = acc[i][0]*scale + maskrow[r0 + kb + 0];
        v.y = acc[i][1]*scale + maskrow[r0 + kb + 1];
        v.z = acc[i][2]*scale + maskrow[r0 + kb + 2];
        v.w = acc[i][3]*scale + maskrow[r0 + kb + 3];
        *(float4*)srow = v;
    }
}

// ---------------------------------------------------------------------------
// Kernel C: row softmax over 2048, in place. 1 block (256 thr) per row.
// ---------------------------------------------------------------------------
__global__ __launch_bounds__(256) void softmax_kernel()
{
    __shared__ float red[8];
    float4* p4 = (float4*)(g_scores + (size_t)blockIdx.x * L_);
    const int t = threadIdx.x;
    const int warp = t >> 5, lane = t & 31;

    float4 a = p4[t];
    float4 b = p4[t + 256];

    // max reduce
    float m = fmaxf(fmaxf(fmaxf(a.x, a.y), fmaxf(a.z, a.w)),
                    fmaxf(fmaxf(b.x, b.y), fmaxf(b.z, b.w)));
#pragma unroll
    for (int o = 16; o > 0; o >>= 1) m = fmaxf(m, __shfl_xor_sync(0xffffffffu, m, o));
    if (lane == 0) red[warp] = m;
    __syncthreads();
    m = red[0];
#pragma unroll
    for (int w = 1; w < 8; w++) m = fmaxf(m, red[w]);
    __syncthreads();

    a.x = __expf(a.x - m); a.y = __expf(a.y - m); a.z = __expf(a.z - m); a.w = __expf(a.w - m);
    b.x = __expf(b.x - m); b.y = __expf(b.y - m); b.z = __expf(b.z - m); b.w = __expf(b.w - m);

    float s = a.x + a.y + a.z + a.w + b.x + b.y + b.z + b.w;
#pragma unroll
    for (int o = 16; o > 0; o >>= 1) s += __shfl_xor_sync(0xffffffffu, s, o);
    if (lane == 0) red[warp] = s;
    __syncthreads();
    s = red[0];
#pragma unroll
    for (int w = 1; w < 8; w++) s += red[w];
    const float inv = 1.0f / s;

    a.x *= inv; a.y *= inv; a.z *= inv; a.w *= inv;
    b.x *= inv; b.y *= inv; b.z *= inv; b.w *= inv;
    p4[t] = a;
    p4[t + 256] = b;
}

// ---------------------------------------------------------------------------
// Kernel D: ctx = probs @ v, per bh.  M=2048 N=64 K=2048.
// BM=128 BN=64 BK=16, 128 threads, 8x8 per thread.
// Output written to [B, L, H] layout.
// ---------------------------------------------------------------------------
__global__ __launch_bounds__(128) void pv_kernel(float* __restrict__ out)
{
    __shared__ float Ast[16][132];   // [k][m-row]
    __shared__ float Bs[16][64];     // [k][n]

    const int bh = blockIdx.y;
    const int m0 = blockIdx.x * 128;
    const float* probs = g_scores + (size_t)bh * L_ * L_;
    const float* v     = g_v      + (size_t)bh * L_ * HD_;

    const int t  = threadIdx.x;
    const int ty = t >> 3;          // 0..15
    const int tx = t & 7;           // 0..7

    float acc[8][8];
#pragma unroll
    for (int i = 0; i < 8; i++)
#pragma unroll
        for (int j = 0; j < 8; j++) acc[i][j] = 0.f;

    const int lc = t & 15, lr = t >> 4;     // A loads
    const int cn = t & 63, kr = t >> 6;     // B loads

    for (int k0 = 0; k0 < L_; k0 += 16) {
#pragma unroll
        for (int it = 0; it < 16; it++)
            Ast[lc][lr + it*8] = probs[(size_t)(m0 + lr + it*8)*L_ + k0 + lc];
#pragma unroll
        for (int it = 0; it < 8; it++)
            Bs[kr + it*2][cn] = v[(size_t)(k0 + kr + it*2)*HD_ + cn];
        __syncthreads();
#pragma unroll
        for (int k = 0; k < 16; k++) {
            float a[8], b[8];
            *(float4*)&a[0] = *(const float4*)&Ast[k][ty*8];
            *(float4*)&a[4] = *(const float4*)&Ast[k][ty*8 + 4];
            *(float4*)&b[0] = *(const float4*)&Bs[k][tx*8];
            *(float4*)&b[4] = *(const float4*)&Bs[k][tx*8 + 4];
#pragma unroll
            for (int i = 0; i < 8; i++)
#pragma unroll
                for (int j = 0; j < 8; j++) acc[i][j] = fmaf(a[i], b[j], acc[i][j]);
        }
        __syncthreads();
    }

    const int b_ = bh >> 4;
    const int h  = bh & 15;
#pragma unroll
    for (int i = 0; i < 8; i++) {
        const int l = m0 + ty*8 + i;
        float* orow = out + ((size_t)b_*L_ + l)*H_ + h*HD_ + tx*8;
        *(float4*)&orow[0] = *(float4*)&acc[i][0];
        *(float4*)&orow[4] = *(float4*)&acc[i][4];
    }
}

// ---------------------------------------------------------------------------
extern "C" void kernel_launch(void* const* d_in, const int* in_sizes, int n_in,
                              void* d_out, int out_size)
{
    const float* hidden   = (const float*)d_in[0];
    const float* mask     = (const float*)d_in[1];
    const float* Wq       = (const float*)d_in[2];
    const float* bq       = (const float*)d_in[3];
    const float* Wk       = (const float*)d_in[4];
    const float* bk       = (const float*)d_in[5];
    const float* Wv       = (const float*)d_in[6];
    const float* bv       = (const float*)d_in[7];
    const float* dist_emb = (const float*)d_in[8];
    float* out            = (float*)d_out;

    cudaFuncSetAttribute(scores_kernel,
                         cudaFuncAttributeMaxDynamicSharedMemorySize, SMEM_B_BYTES);

    // A: QKV projections (z = which weight)
    qkv_kernel<<<dim3(H_/64, M_/128, 3), 128>>>(hidden, Wq, bq, Wk, bk, Wv, bv);

    // B: fused scores + relative position bias + mask + scale
    scores_kernel<<<dim3(L_/64, L_/64, BH_), 256, SMEM_B_BYTES>>>(mask, dist_emb);

    // C: softmax in place
    softmax_kernel<<<BH_*L_, 256>>>();

    // D: probs @ v -> output layout
    pv_kernel<<<dim3(L_/128, BH_), 128>>>(out);
}

// round 3
// speedup vs baseline: 1.0046x; 1.0046x over previous
#include <cuda_runtime.h>
#include <math.h>

// Problem constants
#define B_  2
#define L_  2048
#define H_  1024
#define NH_ 16
#define HD_ 64
#define BH_ (B_*NH_)          // 32
#define M_  (B_*L_)           // 4096
#define MAXPOS_ 2048

// Scratch (device globals — allocation-free contract)
__device__ float g_q[(size_t)BH_*L_*HD_];       // [bh][l][hd]
__device__ float g_k[(size_t)BH_*L_*HD_];
__device__ float g_v[(size_t)BH_*L_*HD_];

// ---------------------------------------------------------------------------
// Kernel A: fused QKV projection.  out = hidden @ W^T + b, written to head
// layout [bh][l][hd].  GEMM M=4096 N=1024 K=1024, per blockIdx.z weight.
// BM=128 BN=64 BK=16, 128 threads, 8x8 per thread.
// ---------------------------------------------------------------------------
__global__ __launch_bounds__(128) void qkv_kernel(
    const float* __restrict__ hidden,
    const float* __restrict__ Wq, const float* __restrict__ bq,
    const float* __restrict__ Wk, const float* __restrict__ bk,
    const float* __restrict__ Wv, const float* __restrict__ bv)
{
    __shared__ float Ast[16][132];   // [k][m-row]
    __shared__ float Bst[16][68];    // [k][n-col]

    const int which = blockIdx.z;
    const float* W   = (which == 0) ? Wq : (which == 1) ? Wk : Wv;
    const float* bia = (which == 0) ? bq : (which == 1) ? bk : bv;
    float* out       = (which == 0) ? g_q : (which == 1) ? g_k : g_v;

    const int m0 = blockIdx.y * 128;
    const int n0 = blockIdx.x * 64;
    const int t  = threadIdx.x;
    const int ty = t >> 3;          // 0..15  -> 8 rows each
    const int tx = t & 7;           // 0..7   -> 8 cols each
    const int lc = t & 15;          // load col (k)
    const int lr = t >> 4;          // load row base 0..7

    float acc[8][8];
#pragma unroll
    for (int i = 0; i < 8; i++)
#pragma unroll
        for (int j = 0; j < 8; j++) acc[i][j] = 0.f;

    for (int k0 = 0; k0 < H_; k0 += 16) {
#pragma unroll
        for (int it = 0; it < 16; it++)
            Ast[lc][lr + it*8] = hidden[(size_t)(m0 + lr + it*8)*H_ + k0 + lc];
#pragma unroll
        for (int it = 0; it < 8; it++)
            Bst[lc][lr + it*8] = W[(size_t)(n0 + lr + it*8)*H_ + k0 + lc];
        __syncthreads();
#pragma unroll
        for (int k = 0; k < 16; k++) {
            float a[8], b[8];
            *(float4*)&a[0] = *(const float4*)&Ast[k][ty*8];
            *(float4*)&a[4] = *(const float4*)&Ast[k][ty*8 + 4];
            *(float4*)&b[0] = *(const float4*)&Bst[k][tx*8];
            *(float4*)&b[4] = *(const float4*)&Bst[k][tx*8 + 4];
#pragma unroll
            for (int i = 0; i < 8; i++)
#pragma unroll
                for (int j = 0; j < 8; j++) acc[i][j] = fmaf(a[i], b[j], acc[i][j]);
        }
        __syncthreads();
    }

    const int h = n0 >> 6;
#pragma unroll
    for (int i = 0; i < 8; i++) {
        const int m  = m0 + ty*8 + i;
        const int b_ = m >> 11;
        const int l  = m & (L_-1);
        float* orow = out + (((size_t)(b_*NH_ + h))*L_ + l)*HD_;
#pragma unroll
        for (int j = 0; j < 8; j++) {
            const int nn = tx*8 + j;                 // hd
            orow[nn] = acc[i][j] + bia[n0 + nn];
        }
    }
}

// ---------------------------------------------------------------------------
// Kernel B (fused flash): for each (bh, 64 l-rows) block, stream over r-tiles:
//   s = (q.k + q.e + k.e)/8 + mask   (diagonal-indexed e-slab in SMEM)
//   online softmax (row max/sum via 16-lane shfl butterflies)
//   o += p @ v  (p transposed through SMEM)
// No score matrix ever touches HBM.
// 256 threads (16x16), 4x4 outputs per thread in both phases.
// SMEM: q,k,p,v tiles 64x68 + e-slab 64x128 = 102400 B.
// ---------------------------------------------------------------------------
#define FLASH_SMEM_BYTES ((4*64*68 + 64*128)*4)

__global__ __launch_bounds__(256) void flash_kernel(
    const float* __restrict__ mask,
    const float* __restrict__ dist_emb,
    float* __restrict__ out)
{
    extern __shared__ float sm[];
    float* qst = sm;                 // [hd][l]  stride 68
    float* kst = sm + 64*68;         // [hd][r]  stride 68
    float* pst = sm + 2*64*68;       // [r][l]   stride 68
    float* vst = sm + 3*64*68;       // [r][hd]  stride 68
    float* est = sm + 4*64*68;       // [hd][dd] stride 128

    const int bh = blockIdx.y;
    const int l0 = blockIdx.x * 64;
    const int t  = threadIdx.x;
    const int tx = t & 15;
    const int ty = t >> 4;

    const float* q = g_q + (size_t)bh * L_ * HD_;
    const float* k = g_k + (size_t)bh * L_ * HD_;
    const float* v = g_v + (size_t)bh * L_ * HD_;
    const float* maskrow = mask + (size_t)(bh >> 4) * L_;   // [B,1,1,L]

    // load q tile transposed once: [hd][l_local]
    {
        const int col  = t & 63;      // hd
        const int row4 = t >> 6;      // 0..3
#pragma unroll
        for (int it = 0; it < 16; it++) {
            const int r_ = row4 + it*4;
            qst[col*68 + r_] = q[(size_t)(l0 + r_)*HD_ + col];
        }
    }

    float o[4][4];
    float mrow[4], lrow[4];
#pragma unroll
    for (int i = 0; i < 4; i++) {
        mrow[i] = -1e30f;
        lrow[i] = 0.f;
#pragma unroll
        for (int c = 0; c < 4; c++) o[i][c] = 0.f;
    }

    const int qb = ty*4, kb = tx*4;
    const int dbase = (ty - tx)*4 + 60;      // 0..120, mult of 4

    for (int r0 = 0; r0 < L_; r0 += 64) {
        // ---- load k (transposed), v (direct), e-slab ----
        {
            const int col  = t & 63;
            const int row4 = t >> 6;
#pragma unroll
            for (int it = 0; it < 16; it++) {
                const int r_ = row4 + it*4;
                kst[col*68 + r_] = k[(size_t)(r0 + r_)*HD_ + col];
                vst[r_*68 + col] = v[(size_t)(r0 + r_)*HD_ + col];
            }
            const int gbase = l0 - r0 + (MAXPOS_ - 1) - 63;   // in [0, 3968]
            for (int idx = t; idx < 64*128; idx += 256) {
                const int dd = idx & 127;
                const int tc = idx >> 7;
                est[tc*128 + dd] = (dd < 127) ? dist_emb[(size_t)(gbase + dd)*HD_ + tc] : 0.f;
            }
        }
        __syncthreads();

        // ---- scores 4x4 ----
        float s[4][4];
#pragma unroll
        for (int i = 0; i < 4; i++)
#pragma unroll
            for (int j = 0; j < 4; j++) s[i][j] = 0.f;

        for (int tt = 0; tt < 64; tt++) {
            float qv[4], kv[4], ev[8];
            *(float4*)&qv[0] = *(const float4*)&qst[tt*68 + qb];
            *(float4*)&kv[0] = *(const float4*)&kst[tt*68 + kb];
            *(float4*)&ev[0] = *(const float4*)&est[tt*128 + dbase];
            *(float4*)&ev[4] = *(const float4*)&est[tt*128 + dbase + 4];
#pragma unroll
            for (int i = 0; i < 4; i++)
#pragma unroll
                for (int j = 0; j < 4; j++) {
                    const int m = i - j + 3;     // ev[m] = e[l-r]
                    s[i][j] = fmaf(qv[i], kv[j], s[i][j]);
                    s[i][j] = fmaf(qv[i] + kv[j], ev[m], s[i][j]);
                }
        }

        // scale + mask
#pragma unroll
        for (int i = 0; i < 4; i++)
#pragma unroll
            for (int j = 0; j < 4; j++)
                s[i][j] = s[i][j]*0.125f + maskrow[r0 + kb + j];

        // ---- online softmax update ----
        float mt[4], st[4], alpha[4];
#pragma unroll
        for (int i = 0; i < 4; i++) {
            mt[i] = fmaxf(fmaxf(s[i][0], s[i][1]), fmaxf(s[i][2], s[i][3]));
#pragma unroll
            for (int off = 8; off > 0; off >>= 1)
                mt[i] = fmaxf(mt[i], __shfl_xor_sync(0xffffffffu, mt[i], off));
            const float mnew = fmaxf(mrow[i], mt[i]);
            alpha[i] = __expf(mrow[i] - mnew);
            mrow[i] = mnew;
            st[i] = 0.f;
#pragma unroll
            for (int j = 0; j < 4; j++) {
                s[i][j] = __expf(s[i][j] - mnew);
                st[i] += s[i][j];
            }
#pragma unroll
            for (int off = 8; off > 0; off >>= 1)
                st[i] += __shfl_xor_sync(0xffffffffu, st[i], off);
            lrow[i] = lrow[i]*alpha[i] + st[i];
#pragma unroll
            for (int c = 0; c < 4; c++) o[i][c] *= alpha[i];
        }

        // ---- store p transposed: pst[r_local][l_local] ----
#pragma unroll
        for (int i = 0; i < 4; i++)
#pragma unroll
            for (int j = 0; j < 4; j++)
                pst[(kb + j)*68 + qb + i] = s[i][j];
        __syncthreads();

        // ---- PV accumulate: o[i][c] += p[l, rr] * v[rr, c] ----
        for (int rr = 0; rr < 64; rr++) {
            float pv_[4], vv[4];
            *(float4*)&pv_[0] = *(const float4*)&pst[rr*68 + qb];
            *(float4*)&vv[0]  = *(const float4*)&vst[rr*68 + kb];
#pragma unroll
            for (int i = 0; i < 4; i++)
#pragma unroll
                for (int c = 0; c < 4; c++)
                    o[i][c] = fmaf(pv_[i], vv[c], o[i][c]);
        }
        __syncthreads();   // protect SMEM tiles before next iteration's loads
    }

    // ---- epilogue: normalize and write [B, L, H] ----
    const int b_ = bh >> 4;
    const int h  = bh & 15;
#pragma unroll
    for (int i = 0; i < 4; i++) {
        const float inv = 1.0f / lrow[i];
        const int l = l0 + qb + i;
        float4 r;
        r.x = o[i][0]*inv; r.y = o[i][1]*inv; r.z = o[i][2]*inv; r.w = o[i][3]*inv;
        *(float4*)&out[((size_t)b_*L_ + l)*H_ + h*HD_ + kb] = r;
    }
}

// ---------------------------------------------------------------------------
extern "C" void kernel_launch(void* const* d_in, const int* in_sizes, int n_in,
                              void* d_out, int out_size)
{
    const float* hidden   = (const float*)d_in[0];
    const float* mask     = (const float*)d_in[1];
    const float* Wq       = (const float*)d_in[2];
    const float* bq       = (const float*)d_in[3];
    const float* Wk       = (const float*)d_in[4];
    const float* bk       = (const float*)d_in[5];
    const float* Wv       = (const float*)d_in[6];
    const float* bv       = (const float*)d_in[7];
    const float* dist_emb = (const float*)d_in[8];
    float* out            = (float*)d_out;

    cudaFuncSetAttribute(flash_kernel,
                         cudaFuncAttributeMaxDynamicSharedMemorySize, FLASH_SMEM_BYTES);

    // A: QKV projections (z = which weight)
    qkv_kernel<<<dim3(H_/64, M_/128, 3), 128>>>(hidden, Wq, bq, Wk, bk, Wv, bv);

    // B: fused scores + bias + softmax + PV
    flash_kernel<<<dim3(L_/64, BH_), 256, FLASH_SMEM_BYTES>>>(mask, dist_emb, out);
}